// round 13
// baseline (speedup 1.0000x reference)
#include <cuda_runtime.h>
#include <cuda_fp16.h>
#include <math.h>
#include <stdint.h>

#define NN 8192
#define DD 128
#define NTILE 64           // 8192/128 tiles
#define TSTRIDE 272        // 128 fp16 cols = 256B data + 16B pad (conflict-free ldmatrix)
#define TILE_B (128 * TSTRIDE)   // 34816 bytes per tile image
#define NJG 32             // j-groups per i-tile
#define JPC 2              // j-tiles per CTA (both resident; no double-buffer reload)

// ---------------- device globals ----------------
__device__ char g_semhi[NTILE * TILE_B];
__device__ char g_xhi[NTILE * TILE_B];
__device__ float g_semnorm[NN];
__device__ float g_xnorm[NN];
__device__ unsigned g_mp[NN];   // max over positives of u = xn - 2*dot (monotone-mapped bits)
__device__ unsigned g_md[NN];   // min over diff-class of u
__device__ unsigned g_ms[NN];   // min over same-class of u

// ---------------- helpers ----------------
__device__ __forceinline__ unsigned fmap(float f) {
    unsigned b = __float_as_uint(f);
    return (b & 0x80000000u) ? ~b : (b | 0x80000000u);
}
__device__ __forceinline__ float funmap(unsigned m) {
    unsigned b = (m & 0x80000000u) ? (m & 0x7FFFFFFFu) : ~m;
    return __uint_as_float(b);
}
__device__ __forceinline__ uint32_t smem_u32(const void* p) {
    uint32_t a;
    asm("{ .reg .u64 t; cvta.to.shared.u64 t, %1; cvt.u32.u64 %0, t; }" : "=r"(a) : "l"(p));
    return a;
}
__device__ __forceinline__ uint64_t gaddr(const void* p) {
    uint64_t a;
    asm("cvta.to.global.u64 %0, %1;" : "=l"(a) : "l"(p));
    return a;
}
#define MBAR_INIT(a, c)   asm volatile("mbarrier.init.shared.b64 [%0], %1;" :: "r"(a), "r"(c) : "memory")
#define MBAR_EXPECT(a, b) asm volatile("mbarrier.arrive.expect_tx.shared.b64 _, [%0], %1;" :: "r"(a), "r"(b) : "memory")
__device__ __forceinline__ void mbar_wait(uint32_t mbar, uint32_t parity) {
    asm volatile(
        "{\n .reg .pred P1;\n"
        "WL_%=:\n mbarrier.try_wait.parity.acquire.cta.shared::cta.b64 P1, [%0], %1, 0x989680;\n"
        "@P1 bra.uni WD_%=;\n bra.uni WL_%=;\n WD_%=:\n}"
        :: "r"(mbar), "r"(parity) : "memory");
}
__device__ __forceinline__ void bulk_g2s(uint32_t dst, uint64_t src, uint32_t bytes, uint32_t mbar) {
    asm volatile("cp.async.bulk.shared::cta.global.mbarrier::complete_tx::bytes [%0], [%1], %2, [%3];"
                 :: "r"(dst), "l"(src), "r"(bytes), "r"(mbar) : "memory");
}
__device__ __forceinline__ void ldm_x4(unsigned* r, uint32_t addr) {
    asm volatile("ldmatrix.sync.aligned.m8n8.x4.shared.b16 {%0,%1,%2,%3}, [%4];"
                 : "=r"(r[0]), "=r"(r[1]), "=r"(r[2]), "=r"(r[3]) : "r"(addr));
}
__device__ __forceinline__ void mma_f16(float* c, const unsigned* a, const unsigned* b) {
    asm volatile("mma.sync.aligned.m16n8k16.row.col.f32.f16.f16.f32 "
                 "{%0,%1,%2,%3}, {%4,%5,%6,%7}, {%8,%9}, {%0,%1,%2,%3};"
                 : "+f"(c[0]), "+f"(c[1]), "+f"(c[2]), "+f"(c[3])
                 : "r"(a[0]), "r"(a[1]), "r"(a[2]), "r"(a[3]), "r"(b[0]), "r"(b[1]));
}

// ---------------------------------------------------------------------------
// Fused prep kernel (heterogeneous grid):
//   blocks [0,128):    sem = alpha*(wv@W^T+b)+(1-alpha)*x -> fp32 out + fp16
//                      tile image + row norms + reduction-cell init
//   blocks [128,1152): x -> fp16 tile image + row norms
__global__ __launch_bounds__(256) void prep_kernel(
    const float* __restrict__ wv, const float* __restrict__ Wm,
    const float* __restrict__ bias, const float* __restrict__ x,
    const float* __restrict__ alpha, float* __restrict__ sem)
{
    __shared__ float As[64 * 50];
    __shared__ float Ws[50 * 128];
    const int t = threadIdx.x;

    if (blockIdx.x >= 128) {
        // ---- convert part: one warp per x row ----
        int row = (blockIdx.x - 128) * 8 + (t >> 5);
        int lid = t & 31;
        float4 v = reinterpret_cast<const float4*>(x + (size_t)row * DD)[lid];
        float s = v.x * v.x + v.y * v.y + v.z * v.z + v.w * v.w;
#pragma unroll
        for (int o = 16; o > 0; o >>= 1) s += __shfl_xor_sync(0xFFFFFFFFu, s, o);
        float f[4] = {v.x, v.y, v.z, v.w};
        unsigned short h[4];
#pragma unroll
        for (int qq = 0; qq < 4; qq++) h[qq] = __half_as_ushort(__float2half_rn(f[qq]));
        unsigned long long hp = (unsigned long long)h[0] | ((unsigned long long)h[1] << 16) |
                                ((unsigned long long)h[2] << 32) | ((unsigned long long)h[3] << 48);
        int tile = row >> 7, rr = row & 127;
        *reinterpret_cast<unsigned long long*>(g_xhi + (size_t)tile * TILE_B + (size_t)rr * TSTRIDE + lid * 8) = hp;
        if (lid == 0) g_xnorm[row] = s;
        return;
    }

    // ---- sem part ----
    const int i0 = blockIdx.x * 64;
    const int tx = t & 15, ty = t >> 4;

    int gtid = blockIdx.x * 256 + t;     // fused init of reduction cells (128*256 = 32768 >= NN)
    if (gtid < NN) {
        g_mp[gtid] = 0u;
        g_md[gtid] = 0xFFFFFFFFu;
        g_ms[gtid] = 0xFFFFFFFFu;
    }

    float acc[4][8];
#pragma unroll
    for (int r = 0; r < 4; r++)
#pragma unroll
        for (int c = 0; c < 8; c++) acc[r][c] = 0.f;
    for (int k0 = 0; k0 < 300; k0 += 50) {
        for (int e = t; e < 64 * 50; e += 256) { int r = e / 50, kk = e % 50; As[e] = wv[(i0 + r) * 300 + k0 + kk]; }
        for (int e = t; e < 50 * 128; e += 256) { int d = e / 50, kk = e % 50; Ws[kk * 128 + d] = Wm[d * 300 + k0 + kk]; }
        __syncthreads();
#pragma unroll 5
        for (int kk = 0; kk < 50; kk++) {
            float a[4], bb[8];
#pragma unroll
            for (int r = 0; r < 4; r++) a[r] = As[(ty * 4 + r) * 50 + kk];
#pragma unroll
            for (int c = 0; c < 8; c++) bb[c] = Ws[kk * 128 + tx * 8 + c];
#pragma unroll
            for (int r = 0; r < 4; r++)
#pragma unroll
                for (int c = 0; c < 8; c++) acc[r][c] = fmaf(a[r], bb[c], acc[r][c]);
        }
        __syncthreads();
    }
#pragma unroll
    for (int r = 0; r < 4; r++) {
        int gi = i0 + ty * 4 + r;
        float al = alpha[gi];
        float v[8];
        float nrm = 0.f;
        unsigned short hh[8];
#pragma unroll
        for (int c = 0; c < 8; c++) {
            int gc = tx * 8 + c;
            float val = al * (acc[r][c] + bias[gc]) + (1.0f - al) * x[gi * DD + gc];
            v[c] = val;
            nrm = fmaf(val, val, nrm);
            hh[c] = __half_as_ushort(__float2half_rn(val));
        }
        float4* semv = reinterpret_cast<float4*>(sem + (size_t)gi * DD + tx * 8);
        semv[0] = make_float4(v[0], v[1], v[2], v[3]);
        semv[1] = make_float4(v[4], v[5], v[6], v[7]);
        int tile = gi >> 7, rr = gi & 127;
        uint4 hp;
        hp.x = (unsigned)hh[0] | ((unsigned)hh[1] << 16);
        hp.y = (unsigned)hh[2] | ((unsigned)hh[3] << 16);
        hp.z = (unsigned)hh[4] | ((unsigned)hh[5] << 16);
        hp.w = (unsigned)hh[6] | ((unsigned)hh[7] << 16);
        *reinterpret_cast<uint4*>(g_semhi + (size_t)tile * TILE_B + (size_t)rr * TSTRIDE + tx * 16) = hp;
#pragma unroll
        for (int o = 1; o <= 8; o <<= 1) nrm += __shfl_xor_sync(0xFFFFFFFFu, nrm, o);
        if (tx == 0) g_semnorm[gi] = nrm;
    }
}

// ---------------------------------------------------------------------------
// Fused fp16 mma.sync pairwise GEMM (1-pass) + batch-hard reduction.
// grid (NJG=32, NTILE=64), 256 threads, warp grid 4x2 (32x64 tile), 2 CTAs/SM.
// A + B0 + B1 all resident: ONE sync total, warps fully decoupled after it.
#define SM_A 0
#define SM_B(j) (TILE_B + (j) * TILE_B)
#define SM_CTRL (3 * TILE_B)
#define SM_MB (SM_CTRL + 0)
#define SM_JINFO (SM_CTRL + 16)
#define SM_TOTAL (SM_CTRL + 16 + 2048)

__global__ void __launch_bounds__(256, 2) dist_kernel(const int* __restrict__ label)
{
    extern __shared__ char smem[];
    const uint32_t sb = smem_u32(smem);
    const int t = threadIdx.x;
    const int lane = t & 31, wid = t >> 5;
    const int wm = wid & 3, wn = wid >> 2;      // warp tile (wm*32 rows, wn*64 cols)
    const int itile = blockIdx.y, jg = blockIdx.x;

    if (t == 0) {
        MBAR_INIT(sb + SM_MB, 1);
        // fence mbar init before async arrive-on from TMA engine
        asm volatile("fence.proxy.async.shared::cta;" ::: "memory");
        MBAR_EXPECT(sb + SM_MB, 3u * TILE_B);
        bulk_g2s(sb + SM_A, gaddr(g_semhi + (size_t)itile * TILE_B), TILE_B, sb + SM_MB);
        bulk_g2s(sb + SM_B(0), gaddr(g_xhi + (size_t)(jg * JPC) * TILE_B), TILE_B, sb + SM_MB);
        bulk_g2s(sb + SM_B(1), gaddr(g_xhi + (size_t)(jg * JPC + 1) * TILE_B), TILE_B, sb + SM_MB);
    }

    // stage jinfo for BOTH tiles: thread t covers global row jg*256 + t
    uint2* jinfo = (uint2*)(smem + SM_JINFO);
    {
        int rowg = jg * (JPC * 128) + t;
        uint2 ji;
        ji.x = __float_as_uint(g_xnorm[rowg]);
        ji.y = (unsigned)label[rowg];
        jinfo[t] = ji;
    }

    // per-thread identity: 4 distinct rows (mt 0/1 x row-half 0/1)
    const int q = lane & 3, rquad = lane >> 2;
    int gi4[4];
    int li[4];
#pragma unroll
    for (int s = 0; s < 4; s++) {
        gi4[s] = itile * 128 + wm * 32 + (s >> 1) * 16 + (s & 1) * 8 + rquad;
        li[s] = label[gi4[s]];
    }
    float mpos[4], msame[4], mdiff[4];
#pragma unroll
    for (int s = 0; s < 4; s++) { mpos[s] = -3.0e38f; msame[s] = 3.0e38f; mdiff[s] = 3.0e38f; }

    // ldmatrix base addresses
    const int lr = lane & 7, grp = lane >> 3;
    const uint32_t aOff0 = (uint32_t)(wm * 32 + (grp & 1) * 8 + lr) * TSTRIDE + (grp >> 1) * 16;
    const uint32_t pA0 = sb + SM_A + aOff0;
    const uint32_t pA1 = pA0 + 16u * TSTRIDE;
    const uint32_t bOff = (uint32_t)(wn * 64 + ((grp >> 1) & 1) * 8 + lr) * TSTRIDE + (grp & 1) * 16;

    __syncthreads();                 // jinfo visible; the ONLY cta-wide sync
    mbar_wait(sb + SM_MB, 0u);       // per-thread; warps decouple from here on

    const uint4* jinfo4 = (const uint4*)(smem + SM_JINFO);

#pragma unroll
    for (int j = 0; j < JPC; j++) {
        const int jt = jg * JPC + j;

        // ---- mainloop: acc = A*B over K=128 (1-pass fp16) ----
        float acc[2][8][4];
#pragma unroll
        for (int mt = 0; mt < 2; mt++)
#pragma unroll
            for (int nt = 0; nt < 8; nt++)
#pragma unroll
                for (int e = 0; e < 4; e++) acc[mt][nt][e] = 0.f;

        const uint32_t pB = sb + SM_B(j) + bOff;
#pragma unroll
        for (int ks = 0; ks < 8; ks++) {
            unsigned ah[2][4], bh[4][4];
            ldm_x4(ah[0], pA0 + ks * 32);
            ldm_x4(ah[1], pA1 + ks * 32);
#pragma unroll
            for (int np = 0; np < 4; np++)
                ldm_x4(bh[np], pB + np * (16 * TSTRIDE) + ks * 32);
#pragma unroll
            for (int np = 0; np < 4; np++)
#pragma unroll
                for (int mt = 0; mt < 2; mt++) {
                    mma_f16(acc[mt][2 * np],     ah[mt], bh[np]);
                    mma_f16(acc[mt][2 * np + 1], ah[mt], bh[np] + 2);
                }
        }

        // ---- epilogue: u = xn[j] - 2*dot, masked max/min into registers ----
#pragma unroll
        for (int nt = 0; nt < 8; nt++) {
            uint4 v = jinfo4[j * 32 + wn * 16 + nt * 2 + (q >> 1)];  // careful: see mapping below
            // NOTE: jinfo is 128 uint2 per tile = 32 uint4 per tile? No: 128 uint2 = 64 uint4.
            (void)v;
            uint4 vv = jinfo4[j * 64 + wn * 32 + nt * 4 + q];  // (xn[jc],lab[jc],xn[jc+1],lab[jc+1])
            float xn0 = __uint_as_float(vv.x), xn1 = __uint_as_float(vv.z);
            int lb0 = (int)vv.y, lb1 = (int)vv.w;
            int gj0 = jt * 128 + wn * 64 + nt * 8 + q * 2;
#pragma unroll
            for (int mt = 0; mt < 2; mt++) {
                const float* a4 = acc[mt][nt];
                int s0 = mt * 2, s1 = mt * 2 + 1;
                float u;
                u = fmaf(-2.f, a4[0], xn0);
                if (lb0 == li[s0]) { msame[s0] = fminf(msame[s0], u); if (gi4[s0] != gj0) mpos[s0] = fmaxf(mpos[s0], u); }
                else mdiff[s0] = fminf(mdiff[s0], u);
                u = fmaf(-2.f, a4[1], xn1);
                if (lb1 == li[s0]) { msame[s0] = fminf(msame[s0], u); if (gi4[s0] != gj0 + 1) mpos[s0] = fmaxf(mpos[s0], u); }
                else mdiff[s0] = fminf(mdiff[s0], u);
                u = fmaf(-2.f, a4[2], xn0);
                if (lb0 == li[s1]) { msame[s1] = fminf(msame[s1], u); if (gi4[s1] != gj0) mpos[s1] = fmaxf(mpos[s1], u); }
                else mdiff[s1] = fminf(mdiff[s1], u);
                u = fmaf(-2.f, a4[3], xn1);
                if (lb1 == li[s1]) { msame[s1] = fminf(msame[s1], u); if (gi4[s1] != gj0 + 1) mpos[s1] = fmaxf(mpos[s1], u); }
                else mdiff[s1] = fminf(mdiff[s1], u);
            }
        }
    }

    // quad reduction (4 lanes share the same rows), then one atomic triple per row
#pragma unroll
    for (int s = 0; s < 4; s++) {
#pragma unroll
        for (int o = 1; o <= 2; o <<= 1) {
            mpos[s] = fmaxf(mpos[s], __shfl_xor_sync(0xFFFFFFFFu, mpos[s], o));
            msame[s] = fminf(msame[s], __shfl_xor_sync(0xFFFFFFFFu, msame[s], o));
            mdiff[s] = fminf(mdiff[s], __shfl_xor_sync(0xFFFFFFFFu, mdiff[s], o));
        }
        if (q == 0) {
            if (mpos[s] > -2.9e38f) atomicMax(&g_mp[gi4[s]], fmap(mpos[s]));
            atomicMin(&g_md[gi4[s]], fmap(mdiff[s]));
            atomicMin(&g_ms[gi4[s]], fmap(msame[s]));
        }
    }
}

// ---------------------------------------------------------------------------
__global__ void final_kernel(float* __restrict__ out) {
    int i = blockIdx.x * blockDim.x + threadIdx.x;
    if (i >= NN) return;
    const float DEPS = (float)DD * 1e-16f;
    float sn = g_semnorm[i];
    unsigned mp = g_mp[i], md = g_md[i], ms = g_ms[i];
    float fp = (mp == 0u) ? 0.f : sqrtf(fmaxf(sn + funmap(mp), 0.f) + DEPS);
    float d1 = (md == 0xFFFFFFFFu) ? 3.0e38f : sqrtf(fmaxf(sn + funmap(md), 0.f) + DEPS);
    float d2 = (ms == 0xFFFFFFFFu) ? 3.0e38f : sqrtf(fmaxf(sn + funmap(ms), 0.f) + DEPS) + 1e8f;
    float cn = fminf(d1, d2);
    float z = fp - cn;
    out[i] = fmaxf(z, 0.f) + log1pf(expf(-fabsf(z)));
}

// ---------------------------------------------------------------------------
extern "C" void kernel_launch(void* const* d_in, const int* in_sizes, int n_in,
                              void* d_out, int out_size)
{
    const float* x = (const float*)d_in[0];
    const float* wv = (const float*)d_in[1];
    const int* label = (const int*)d_in[2];
    const float* alpha = (const float*)d_in[3];
    const float* Wm = (const float*)d_in[4];
    const float* bias = (const float*)d_in[5];

    float* out = (float*)d_out;       // [N] diff, then [N,D] sem
    float* sem = out + NN;

    cudaFuncSetAttribute(dist_kernel, cudaFuncAttributeMaxDynamicSharedMemorySize, SM_TOTAL);

    prep_kernel<<<128 + NN / 8, 256>>>(wv, Wm, bias, x, alpha, sem);
    dim3 grid(NJG, NTILE);
    dist_kernel<<<grid, 256, SM_TOTAL>>>(label);
    final_kernel<<<(NN + 255) / 256, 256>>>(out);
}

// round 14
// speedup vs baseline: 1.3401x; 1.3401x over previous
#include <cuda_runtime.h>
#include <cuda_fp16.h>
#include <math.h>
#include <stdint.h>

#define NN 8192
#define DD 128
#define NTILE 64           // 8192/128 tiles
#define TSTRIDE 272        // 128 fp16 cols = 256B data + 16B pad (conflict-free ldmatrix)
#define TILE_B (128 * TSTRIDE)   // 34816 bytes per tile image
#define NJG 32             // j-groups per i-tile
#define JPC 2              // j-tiles per CTA (both resident; no double-buffer reload)

// ---------------- device globals ----------------
__device__ char g_semhi[NTILE * TILE_B];
__device__ char g_xhi[NTILE * TILE_B];
__device__ float g_semnorm[NN];
__device__ float g_xnorm[NN];
__device__ unsigned g_mp[NN];   // max over positives of u = xn - 2*dot (monotone-mapped bits)
__device__ unsigned g_md[NN];   // min over diff-class of u
__device__ unsigned g_ms[NN];   // min over same-class of u

// ---------------- helpers ----------------
__device__ __forceinline__ unsigned fmap(float f) {
    unsigned b = __float_as_uint(f);
    return (b & 0x80000000u) ? ~b : (b | 0x80000000u);
}
__device__ __forceinline__ float funmap(unsigned m) {
    unsigned b = (m & 0x80000000u) ? (m & 0x7FFFFFFFu) : ~m;
    return __uint_as_float(b);
}
__device__ __forceinline__ uint32_t smem_u32(const void* p) {
    uint32_t a;
    asm("{ .reg .u64 t; cvta.to.shared.u64 t, %1; cvt.u32.u64 %0, t; }" : "=r"(a) : "l"(p));
    return a;
}
__device__ __forceinline__ uint64_t gaddr(const void* p) {
    uint64_t a;
    asm("cvta.to.global.u64 %0, %1;" : "=l"(a) : "l"(p));
    return a;
}
#define MBAR_INIT(a, c)   asm volatile("mbarrier.init.shared.b64 [%0], %1;" :: "r"(a), "r"(c) : "memory")
#define MBAR_EXPECT(a, b) asm volatile("mbarrier.arrive.expect_tx.shared.b64 _, [%0], %1;" :: "r"(a), "r"(b) : "memory")
__device__ __forceinline__ void mbar_wait(uint32_t mbar, uint32_t parity) {
    asm volatile(
        "{\n .reg .pred P1;\n"
        "WL_%=:\n mbarrier.try_wait.parity.acquire.cta.shared::cta.b64 P1, [%0], %1, 0x989680;\n"
        "@P1 bra.uni WD_%=;\n bra.uni WL_%=;\n WD_%=:\n}"
        :: "r"(mbar), "r"(parity) : "memory");
}
__device__ __forceinline__ void bulk_g2s(uint32_t dst, uint64_t src, uint32_t bytes, uint32_t mbar) {
    asm volatile("cp.async.bulk.shared::cta.global.mbarrier::complete_tx::bytes [%0], [%1], %2, [%3];"
                 :: "r"(dst), "l"(src), "r"(bytes), "r"(mbar) : "memory");
}
__device__ __forceinline__ void ldm_x4(unsigned* r, uint32_t addr) {
    asm volatile("ldmatrix.sync.aligned.m8n8.x4.shared.b16 {%0,%1,%2,%3}, [%4];"
                 : "=r"(r[0]), "=r"(r[1]), "=r"(r[2]), "=r"(r[3]) : "r"(addr));
}
__device__ __forceinline__ void mma_f16(float* c, const unsigned* a, const unsigned* b) {
    asm volatile("mma.sync.aligned.m16n8k16.row.col.f32.f16.f16.f32 "
                 "{%0,%1,%2,%3}, {%4,%5,%6,%7}, {%8,%9}, {%0,%1,%2,%3};"
                 : "+f"(c[0]), "+f"(c[1]), "+f"(c[2]), "+f"(c[3])
                 : "r"(a[0]), "r"(a[1]), "r"(a[2]), "r"(a[3]), "r"(b[0]), "r"(b[1]));
}

// ---------------------------------------------------------------------------
// prep: 128 blocks. Per block: (1) convert 64 x-rows -> fp16 image + norms
// (warp-per-row prelude), (2) init reduction cells, (3) sem GEMM tile of 64
// rows -> fp32 sem out + fp16 image + norms.
__global__ __launch_bounds__(256) void prep_kernel(
    const float* __restrict__ wv, const float* __restrict__ Wm,
    const float* __restrict__ bias, const float* __restrict__ x,
    const float* __restrict__ alpha, float* __restrict__ sem)
{
    __shared__ float As[64 * 50];
    __shared__ float Ws[50 * 128];
    const int i0 = blockIdx.x * 64;
    const int t = threadIdx.x;
    const int tx = t & 15, ty = t >> 4;
    const int wrp = t >> 5, lid = t & 31;

    // ---- prelude: convert x rows [i0, i0+64) ----
#pragma unroll
    for (int it = 0; it < 8; it++) {
        int row = i0 + wrp * 8 + it;
        float4 v = reinterpret_cast<const float4*>(x + (size_t)row * DD)[lid];
        float s = v.x * v.x + v.y * v.y + v.z * v.z + v.w * v.w;
#pragma unroll
        for (int o = 16; o > 0; o >>= 1) s += __shfl_xor_sync(0xFFFFFFFFu, s, o);
        unsigned short h[4];
        h[0] = __half_as_ushort(__float2half_rn(v.x));
        h[1] = __half_as_ushort(__float2half_rn(v.y));
        h[2] = __half_as_ushort(__float2half_rn(v.z));
        h[3] = __half_as_ushort(__float2half_rn(v.w));
        unsigned long long hp = (unsigned long long)h[0] | ((unsigned long long)h[1] << 16) |
                                ((unsigned long long)h[2] << 32) | ((unsigned long long)h[3] << 48);
        int tile = row >> 7, rr = row & 127;
        *reinterpret_cast<unsigned long long*>(g_xhi + (size_t)tile * TILE_B + (size_t)rr * TSTRIDE + lid * 8) = hp;
        if (lid == 0) g_xnorm[row] = s;
    }

    // ---- fused init of reduction cells (128*256 = 32768 >= NN covers 64/blk) ----
    int gtid = blockIdx.x * 64 + (t & 63);     // each cell hit 4x; idempotent stores
    if (t < 64) {
        g_mp[i0 + t] = 0u;
        g_md[i0 + t] = 0xFFFFFFFFu;
        g_ms[i0 + t] = 0xFFFFFFFFu;
    }
    (void)gtid;

    // ---- sem GEMM ----
    float acc[4][8];
#pragma unroll
    for (int r = 0; r < 4; r++)
#pragma unroll
        for (int c = 0; c < 8; c++) acc[r][c] = 0.f;
    for (int k0 = 0; k0 < 300; k0 += 50) {
        for (int e = t; e < 64 * 50; e += 256) { int r = e / 50, kk = e % 50; As[e] = wv[(i0 + r) * 300 + k0 + kk]; }
        for (int e = t; e < 50 * 128; e += 256) { int d = e / 50, kk = e % 50; Ws[kk * 128 + d] = Wm[d * 300 + k0 + kk]; }
        __syncthreads();
#pragma unroll 5
        for (int kk = 0; kk < 50; kk++) {
            float a[4], bb[8];
#pragma unroll
            for (int r = 0; r < 4; r++) a[r] = As[(ty * 4 + r) * 50 + kk];
#pragma unroll
            for (int c = 0; c < 8; c++) bb[c] = Ws[kk * 128 + tx * 8 + c];
#pragma unroll
            for (int r = 0; r < 4; r++)
#pragma unroll
                for (int c = 0; c < 8; c++) acc[r][c] = fmaf(a[r], bb[c], acc[r][c]);
        }
        __syncthreads();
    }
#pragma unroll
    for (int r = 0; r < 4; r++) {
        int gi = i0 + ty * 4 + r;
        float al = alpha[gi];
        float v[8];
        float nrm = 0.f;
        unsigned short hh[8];
#pragma unroll
        for (int c = 0; c < 8; c++) {
            int gc = tx * 8 + c;
            float val = al * (acc[r][c] + bias[gc]) + (1.0f - al) * x[gi * DD + gc];
            v[c] = val;
            nrm = fmaf(val, val, nrm);
            hh[c] = __half_as_ushort(__float2half_rn(val));
        }
        float4* semv = reinterpret_cast<float4*>(sem + (size_t)gi * DD + tx * 8);
        semv[0] = make_float4(v[0], v[1], v[2], v[3]);
        semv[1] = make_float4(v[4], v[5], v[6], v[7]);
        int tile = gi >> 7, rr = gi & 127;
        uint4 hp;
        hp.x = (unsigned)hh[0] | ((unsigned)hh[1] << 16);
        hp.y = (unsigned)hh[2] | ((unsigned)hh[3] << 16);
        hp.z = (unsigned)hh[4] | ((unsigned)hh[5] << 16);
        hp.w = (unsigned)hh[6] | ((unsigned)hh[7] << 16);
        *reinterpret_cast<uint4*>(g_semhi + (size_t)tile * TILE_B + (size_t)rr * TSTRIDE + tx * 16) = hp;
#pragma unroll
        for (int o = 1; o <= 8; o <<= 1) nrm += __shfl_xor_sync(0xFFFFFFFFu, nrm, o);
        if (tx == 0) g_semnorm[gi] = nrm;
    }
}

// ---------------------------------------------------------------------------
// Fused fp16 mma.sync pairwise GEMM (1-pass) + batch-hard reduction.
// grid (NJG=32, NTILE=64), 256 threads, warp grid 4x2 (32x64 tile), 2 CTAs/SM.
// A + B0 + B1 all resident: ONE cta sync total; warps decouple after it.
#define SM_A 0
#define SM_B(j) (TILE_B + (j) * TILE_B)
#define SM_CTRL (3 * TILE_B)
#define SM_MB (SM_CTRL + 0)
#define SM_JINFO (SM_CTRL + 16)
#define SM_TOTAL (SM_CTRL + 16 + 2048)

__global__ void __launch_bounds__(256, 2) dist_kernel(const int* __restrict__ label)
{
    extern __shared__ char smem[];
    const uint32_t sb = smem_u32(smem);
    const int t = threadIdx.x;
    const int lane = t & 31, wid = t >> 5;
    const int wm = wid & 3, wn = wid >> 2;      // warp tile (wm*32 rows, wn*64 cols)
    const int itile = blockIdx.y, jg = blockIdx.x;

    if (t == 0) {
        MBAR_INIT(sb + SM_MB, 1);
        asm volatile("fence.proxy.async.shared::cta;" ::: "memory");
        MBAR_EXPECT(sb + SM_MB, 3u * TILE_B);
        bulk_g2s(sb + SM_A, gaddr(g_semhi + (size_t)itile * TILE_B), TILE_B, sb + SM_MB);
        bulk_g2s(sb + SM_B(0), gaddr(g_xhi + (size_t)(jg * JPC) * TILE_B), TILE_B, sb + SM_MB);
        bulk_g2s(sb + SM_B(1), gaddr(g_xhi + (size_t)(jg * JPC + 1) * TILE_B), TILE_B, sb + SM_MB);
    }

    // stage jinfo for BOTH tiles: thread t covers global row jg*256 + t
    uint2* jinfo = (uint2*)(smem + SM_JINFO);
    {
        int rowg = jg * (JPC * 128) + t;
        uint2 ji;
        ji.x = __float_as_uint(g_xnorm[rowg]);
        ji.y = (unsigned)label[rowg];
        jinfo[t] = ji;
    }

    // per-thread identity: 4 distinct rows (mt 0/1 x row-half 0/1)
    const int q = lane & 3, rquad = lane >> 2;
    int gi4[4];
    int li[4];
#pragma unroll
    for (int s = 0; s < 4; s++) {
        gi4[s] = itile * 128 + wm * 32 + (s >> 1) * 16 + (s & 1) * 8 + rquad;
        li[s] = label[gi4[s]];
    }
    float mpos[4], msame[4], mdiff[4];
#pragma unroll
    for (int s = 0; s < 4; s++) { mpos[s] = -3.0e38f; msame[s] = 3.0e38f; mdiff[s] = 3.0e38f; }

    // ldmatrix base addresses
    const int lr = lane & 7, grp = lane >> 3;
    const uint32_t aOff0 = (uint32_t)(wm * 32 + (grp & 1) * 8 + lr) * TSTRIDE + (grp >> 1) * 16;
    const uint32_t pA0 = sb + SM_A + aOff0;
    const uint32_t pA1 = pA0 + 16u * TSTRIDE;
    const uint32_t bOff = (uint32_t)(wn * 64 + ((grp >> 1) & 1) * 8 + lr) * TSTRIDE + (grp & 1) * 16;

    __syncthreads();                 // jinfo visible; the ONLY cta-wide sync
    mbar_wait(sb + SM_MB, 0u);       // per-thread; warps decouple from here on

    const uint4* jinfo4 = (const uint4*)(smem + SM_JINFO);

#pragma unroll
    for (int j = 0; j < JPC; j++) {
        const int jt = jg * JPC + j;

        // ---- mainloop: acc = A*B over K=128 (1-pass fp16) ----
        float acc[2][8][4];
#pragma unroll
        for (int mt = 0; mt < 2; mt++)
#pragma unroll
            for (int nt = 0; nt < 8; nt++)
#pragma unroll
                for (int e = 0; e < 4; e++) acc[mt][nt][e] = 0.f;

        const uint32_t pB = sb + SM_B(j) + bOff;
#pragma unroll
        for (int ks = 0; ks < 8; ks++) {
            unsigned ah[2][4], bh[4][4];
            ldm_x4(ah[0], pA0 + ks * 32);
            ldm_x4(ah[1], pA1 + ks * 32);
#pragma unroll
            for (int np = 0; np < 4; np++)
                ldm_x4(bh[np], pB + np * (16 * TSTRIDE) + ks * 32);
#pragma unroll
            for (int np = 0; np < 4; np++)
#pragma unroll
                for (int mt = 0; mt < 2; mt++) {
                    mma_f16(acc[mt][2 * np],     ah[mt], bh[np]);
                    mma_f16(acc[mt][2 * np + 1], ah[mt], bh[np] + 2);
                }
        }

        // ---- epilogue: u = xn[j] - 2*dot, masked max/min into registers ----
#pragma unroll
        for (int nt = 0; nt < 8; nt++) {
            uint4 vv = jinfo4[j * 64 + wn * 32 + nt * 4 + q];  // (xn[jc],lab[jc],xn[jc+1],lab[jc+1])
            float xn0 = __uint_as_float(vv.x), xn1 = __uint_as_float(vv.z);
            int lb0 = (int)vv.y, lb1 = (int)vv.w;
            int gj0 = jt * 128 + wn * 64 + nt * 8 + q * 2;
#pragma unroll
            for (int mt = 0; mt < 2; mt++) {
                const float* a4 = acc[mt][nt];
                int s0 = mt * 2, s1 = mt * 2 + 1;
                float u;
                u = fmaf(-2.f, a4[0], xn0);
                if (lb0 == li[s0]) { msame[s0] = fminf(msame[s0], u); if (gi4[s0] != gj0) mpos[s0] = fmaxf(mpos[s0], u); }
                else mdiff[s0] = fminf(mdiff[s0], u);
                u = fmaf(-2.f, a4[1], xn1);
                if (lb1 == li[s0]) { msame[s0] = fminf(msame[s0], u); if (gi4[s0] != gj0 + 1) mpos[s0] = fmaxf(mpos[s0], u); }
                else mdiff[s0] = fminf(mdiff[s0], u);
                u = fmaf(-2.f, a4[2], xn0);
                if (lb0 == li[s1]) { msame[s1] = fminf(msame[s1], u); if (gi4[s1] != gj0) mpos[s1] = fmaxf(mpos[s1], u); }
                else mdiff[s1] = fminf(mdiff[s1], u);
                u = fmaf(-2.f, a4[3], xn1);
                if (lb1 == li[s1]) { msame[s1] = fminf(msame[s1], u); if (gi4[s1] != gj0 + 1) mpos[s1] = fmaxf(mpos[s1], u); }
                else mdiff[s1] = fminf(mdiff[s1], u);
            }
        }
    }

    // quad reduction (4 lanes share the same rows), then one atomic triple per row
#pragma unroll
    for (int s = 0; s < 4; s++) {
#pragma unroll
        for (int o = 1; o <= 2; o <<= 1) {
            mpos[s] = fmaxf(mpos[s], __shfl_xor_sync(0xFFFFFFFFu, mpos[s], o));
            msame[s] = fminf(msame[s], __shfl_xor_sync(0xFFFFFFFFu, msame[s], o));
            mdiff[s] = fminf(mdiff[s], __shfl_xor_sync(0xFFFFFFFFu, mdiff[s], o));
        }
        if (q == 0) {
            if (mpos[s] > -2.9e38f) atomicMax(&g_mp[gi4[s]], fmap(mpos[s]));
            atomicMin(&g_md[gi4[s]], fmap(mdiff[s]));
            atomicMin(&g_ms[gi4[s]], fmap(msame[s]));
        }
    }
}

// ---------------------------------------------------------------------------
__global__ void final_kernel(float* __restrict__ out) {
    int i = blockIdx.x * blockDim.x + threadIdx.x;
    if (i >= NN) return;
    const float DEPS = (float)DD * 1e-16f;
    float sn = g_semnorm[i];
    unsigned mp = g_mp[i], md = g_md[i], ms = g_ms[i];
    float fp = (mp == 0u) ? 0.f : sqrtf(fmaxf(sn + funmap(mp), 0.f) + DEPS);
    float d1 = (md == 0xFFFFFFFFu) ? 3.0e38f : sqrtf(fmaxf(sn + funmap(md), 0.f) + DEPS);
    float d2 = (ms == 0xFFFFFFFFu) ? 3.0e38f : sqrtf(fmaxf(sn + funmap(ms), 0.f) + DEPS) + 1e8f;
    float cn = fminf(d1, d2);
    float z = fp - cn;
    out[i] = fmaxf(z, 0.f) + log1pf(expf(-fabsf(z)));
}

// ---------------------------------------------------------------------------
extern "C" void kernel_launch(void* const* d_in, const int* in_sizes, int n_in,
                              void* d_out, int out_size)
{
    const float* x = (const float*)d_in[0];
    const float* wv = (const float*)d_in[1];
    const int* label = (const int*)d_in[2];
    const float* alpha = (const float*)d_in[3];
    const float* Wm = (const float*)d_in[4];
    const float* bias = (const float*)d_in[5];

    float* out = (float*)d_out;       // [N] diff, then [N,D] sem
    float* sem = out + NN;

    cudaFuncSetAttribute(dist_kernel, cudaFuncAttributeMaxDynamicSharedMemorySize, SM_TOTAL);

    prep_kernel<<<128, 256>>>(wv, Wm, bias, x, alpha, sem);
    dim3 grid(NJG, NTILE);
    dist_kernel<<<grid, 256, SM_TOTAL>>>(label);
    final_kernel<<<(NN + 255) / 256, 256>>>(out);
}